// round 7
// baseline (speedup 1.0000x reference)
#include <cuda_runtime.h>
#include <math.h>

// ---------------- device scratch (no dynamic allocation allowed) ----------------
__device__ __align__(16) float g_bufA[16777216];   // 2*128*256*256 floats = 64MB
__device__ __align__(16) float g_bufB[16777216];
__device__ __align__(16) float2 g_P[524288];       // B*256*4*256
__device__ __align__(16) float2 g_xf[8192];        // B*256*16
__device__ __align__(16) float2 g_of[4096];        // B*128*16
__device__ __align__(16) float2 g_T[262144];       // B*128*256*4
__device__ float g_c256[256];
__device__ float g_s256[256];

__device__ __forceinline__ float wsum(float v) {
#pragma unroll
    for (int o = 16; o; o >>= 1) v += __shfl_xor_sync(0xffffffffu, v, o);
    return v;
}

// packed fp32x2 FMA: d = a*b + d  (per-lane IEEE fp32, 2x FMA-pipe throughput)
__device__ __forceinline__ void ffma2(float2& d, float2 a, float2 b) {
    unsigned long long& du = reinterpret_cast<unsigned long long&>(d);
    asm("fma.rn.f32x2 %0, %1, %2, %0;"
        : "+l"(du)
        : "l"(reinterpret_cast<unsigned long long&>(a)),
          "l"(reinterpret_cast<unsigned long long&>(b)));
}

// cos/sin(2*pi*t/256) tables built in double precision
__global__ void k_tables() {
    int t = threadIdx.x;
    double a = (double)t / 128.0;          // pi*t/128 = 2*pi*t/256
    g_c256[t] = (float)cospi(a);
    g_s256[t] = (float)sinpi(a);
}

// Stage 1: P[bi][l][h] = sum_w x[bi,h,w] * e^{-i 2pi l w/256}, l=0..3 (raw sums)
__global__ void k_fwd_w(const float* __restrict__ x) {
    __shared__ float cs[256], ss[256];
    int tid = threadIdx.x;
    cs[tid] = g_c256[tid];
    ss[tid] = g_s256[tid];
    __syncthreads();
    int warp = tid >> 5, lane = tid & 31;
    int row = blockIdx.x * 8 + warp;       // row < B*C*256 (grid exact)
    int bi = row >> 8;
    int h = row & 255;
    const float* xp = x + ((long)bi << 16) + (h << 8);
    float re0 = 0, re1 = 0, re2 = 0, re3 = 0, im1 = 0, im2 = 0, im3 = 0;
    for (int w = lane; w < 256; w += 32) {
        float v = xp[w];
        int m1 = w, m2 = (2 * w) & 255, m3 = (3 * w) & 255;
        re0 += v;
        re1 += v * cs[m1]; im1 -= v * ss[m1];
        re2 += v * cs[m2]; im2 -= v * ss[m2];
        re3 += v * cs[m3]; im3 -= v * ss[m3];
    }
    re0 = wsum(re0); re1 = wsum(re1); re2 = wsum(re2); re3 = wsum(re3);
    im1 = wsum(im1); im2 = wsum(im2); im3 = wsum(im3);
    if (lane == 0) {
        float2* Pp = g_P + ((long)bi << 10) + h;
        Pp[0]   = make_float2(re0, 0.f);
        Pp[256] = make_float2(re1, im1);
        Pp[512] = make_float2(re2, im2);
        Pp[768] = make_float2(re3, im3);
    }
}

// Stage 2: xf[bi][k][l] = sum_h P[bi][l][h] * e^{-i 2pi k h/256}, k=0..3
__global__ void k_fwd_h() {
    __shared__ float cs[256], ss[256];
    int tid = threadIdx.x;
    cs[tid] = g_c256[tid];
    ss[tid] = g_s256[tid];
    __syncthreads();
    int warp = tid >> 5, lane = tid & 31;
    int idx = blockIdx.x * 8 + warp;       // idx < B*C*4 (grid exact)
    int bi = idx >> 2;
    int l = idx & 3;
    const float2* Pp = g_P + ((long)bi << 10) + (l << 8);
    float xr0 = 0, xr1 = 0, xr2 = 0, xr3 = 0, xi0 = 0, xi1 = 0, xi2 = 0, xi3 = 0;
    for (int h = lane; h < 256; h += 32) {
        float2 p = Pp[h];
        int m1 = h, m2 = (2 * h) & 255, m3 = (3 * h) & 255;
        xr0 += p.x; xi0 += p.y;
        float c, s;
        c = cs[m1]; s = ss[m1]; xr1 += p.x * c + p.y * s; xi1 += p.y * c - p.x * s;
        c = cs[m2]; s = ss[m2]; xr2 += p.x * c + p.y * s; xi2 += p.y * c - p.x * s;
        c = cs[m3]; s = ss[m3]; xr3 += p.x * c + p.y * s; xi3 += p.y * c - p.x * s;
    }
    xr0 = wsum(xr0); xr1 = wsum(xr1); xr2 = wsum(xr2); xr3 = wsum(xr3);
    xi0 = wsum(xi0); xi1 = wsum(xi1); xi2 = wsum(xi2); xi3 = wsum(xi3);
    if (lane == 0) {
        float2* xfp = g_xf + ((long)bi << 4) + l;
        xfp[0]  = make_float2(xr0, xi0);
        xfp[4]  = make_float2(xr1, xi1);
        xfp[8]  = make_float2(xr2, xi2);
        xfp[12] = make_float2(xr3, xi3);
    }
}

// of[b][o][k][l] = sum_i xf[b][i][k][l] * (wr + i*wi)[i][o][k][l]
__global__ void k_mix(const float* __restrict__ wr, const float* __restrict__ wi,
                      int IC, int OC) {
    int tid = threadIdx.x;
    int warp = tid >> 5, lane = tid & 31;
    int idx = blockIdx.x * 8 + warp;       // idx < B*OC*16 (grid exact)
    int kl = idx & 15;
    int bo = idx >> 4;
    int b = bo / OC, o = bo - b * OC;
    float ar = 0, ai = 0;
    for (int i = lane; i < IC; i += 32) {
        float2 xv = g_xf[(((long)b * IC + i) << 4) + kl];
        long wb = ((long)i * OC + o) * 16 + kl;
        float wrv = wr[wb];
        float wiv = wi[wb];
        ar += xv.x * wrv - xv.y * wiv;
        ai += xv.x * wiv + xv.y * wrv;
    }
    ar = wsum(ar); ai = wsum(ai);
    if (lane == 0) g_of[idx] = make_float2(ar, ai);
}

// T[bo][h][l] = c_l/65536 * sum_k of[bo][k][l] * e^{+i 2pi k h/256}
__global__ void k_makeT() {
    int tid = blockIdx.x * 256 + threadIdx.x;   // < B*OC*1024 (grid exact)
    int l = tid & 3;
    int h = (tid >> 2) & 255;
    int bo = tid >> 10;
    float tr = 0, ti = 0;
#pragma unroll
    for (int k = 0; k < 4; k++) {
        float2 o = g_of[(bo << 4) + (k << 2) + l];
        int m = (k * h) & 255;
        float c = g_c256[m], s = g_s256[m];
        tr += o.x * c - o.y * s;
        ti += o.x * s + o.y * c;
    }
    float sc = (l == 0 ? 1.f : 2.f) * (1.f / 65536.f);
    g_T[tid] = make_float2(tr * sc, ti * sc);
}

// Fused: out = gelu( conv1x1(x,bw) + bb + synth(T) ) + skip
// GEMM tile 64oc x 128px, K-step 8, 8x8 register blocks (f32x2 along px).
__launch_bounds__(128, 4)
__global__ void k_fno_out(const float* __restrict__ x, const float* __restrict__ bw,
                          const float* __restrict__ bb, const float* __restrict__ skip,
                          float* __restrict__ out, int IC, int OC) {
    __shared__ __align__(16) float As[8][64];
    __shared__ __align__(16) float Xs[8][128];
    __shared__ float csS[256], ssS[256];
    int tid = threadIdx.x;
    csS[tid] = g_c256[tid]; csS[tid + 128] = g_c256[tid + 128];
    ssS[tid] = g_s256[tid]; ssS[tid + 128] = g_s256[tid + 128];
    int b = blockIdx.z;
    int oc_base = blockIdx.y * 64;
    int px_base = blockIdx.x * 128;
    const float* xb = x + (long)b * IC * 65536;
    int ocg = tid & 7, pxg = tid >> 3;
    int px0 = pxg * 8;
    float2 acc[8][4];
#pragma unroll
    for (int i = 0; i < 8; i++)
#pragma unroll
        for (int j = 0; j < 4; j++) acc[i][j] = make_float2(0.f, 0.f);

    for (int k0 = 0; k0 < IC; k0 += 8) {
        __syncthreads();
#pragma unroll
        for (int t = tid; t < 512; t += 128) {
            int oc = t >> 3, kk = t & 7;
            int go = oc_base + oc;
            As[kk][oc] = (go < OC) ? bw[(long)go * IC + k0 + kk] : 0.f;
        }
#pragma unroll
        for (int t = tid; t < 1024; t += 128) {
            int kk = t >> 7, px = t & 127;
            Xs[kk][px] = xb[((long)(k0 + kk) << 16) + px_base + px];
        }
        __syncthreads();
#pragma unroll
        for (int kk = 0; kk < 8; kk++) {
            float4 a0 = *(const float4*)&As[kk][ocg * 8];
            float4 a1 = *(const float4*)&As[kk][ocg * 8 + 4];
            float4 v0 = *(const float4*)&Xs[kk][px0];
            float4 v1 = *(const float4*)&Xs[kk][px0 + 4];
            float av[8] = {a0.x, a0.y, a0.z, a0.w, a1.x, a1.y, a1.z, a1.w};
            float2 xp[4] = {make_float2(v0.x, v0.y), make_float2(v0.z, v0.w),
                            make_float2(v1.x, v1.y), make_float2(v1.z, v1.w)};
#pragma unroll
            for (int i = 0; i < 8; i++) {
                float2 ab = make_float2(av[i], av[i]);
#pragma unroll
                for (int j = 0; j < 4; j++) ffma2(acc[i][j], xp[j], ab);
            }
        }
    }
    // epilogue: synth + bias + exact gelu + skip
    int p00 = px_base + px0;
    int h = p00 >> 8;                       // 128-px tile never crosses a row
#pragma unroll
    for (int i = 0; i < 8; i++) {
        int oc = oc_base + ocg * 8 + i;
        if (oc >= OC) break;
        float bias = bb[oc];
        const float2* Tp = g_T + ((((long)b * OC + oc) << 8) + h) * 4;
        float4 t01 = *(const float4*)(Tp);      // T0.re, T0.im, T1.re, T1.im
        float4 t23 = *(const float4*)(Tp + 2);  // T2.re, T2.im, T3.re, T3.im
        long dstb = (((long)b * OC + oc) << 16);
#pragma unroll
        for (int j = 0; j < 8; j++) {
            int p = p00 + j;
            int w = p & 255;
            int m1 = w, m2 = (2 * w) & 255, m3 = (3 * w) & 255;
            float synth = t01.x;
            synth += t01.z * csS[m1] - t01.w * ssS[m1];
            synth += t23.x * csS[m2] - t23.y * ssS[m2];
            synth += t23.z * csS[m3] - t23.w * ssS[m3];
            float a = (j & 1) ? acc[i][j >> 1].y : acc[i][j >> 1].x;
            float v = a + bias + synth;
            float g = 0.5f * v * (1.f + erff(v * 0.70710678118654752f));
            out[dstb + p] = g + skip[dstb + p];
        }
    }
}

// 3x3 SAME conv + bias + ReLU. Tile: 16oc x 16h x 16w, 128 threads,
// per-thread 4oc x 2h x 4w register block, f32x2 packed along w.
__launch_bounds__(128)
__global__ void k_conv3x3_relu(const float* __restrict__ in, const float* __restrict__ w,
                               const float* __restrict__ bias, float* __restrict__ out,
                               int C) {
    __shared__ __align__(16) float s_in[18][20];
    __shared__ __align__(16) float2 s_w2[16][9];
    int tid = threadIdx.x;
    int ocgc = C >> 4;
    int b = blockIdx.z / ocgc;
    int oc_base = (blockIdx.z - b * ocgc) << 4;
    int h_base = blockIdx.y << 4;
    int w_base = blockIdx.x << 4;
    int ocq = tid & 3;
    int pg = tid >> 2;
    int h0 = (pg >> 2) << 1;
    int w0 = (pg & 3) << 2;
    float2 acc[4][2][2];   // [oc][ih][wpair]; wpair0 -> (w0,w0+1), wpair1 -> (w0+2,w0+3)
#pragma unroll
    for (int j = 0; j < 4; j++)
#pragma unroll
        for (int ih = 0; ih < 2; ih++) {
            acc[j][ih][0] = make_float2(0.f, 0.f);
            acc[j][ih][1] = make_float2(0.f, 0.f);
        }
    const float* inb = in + (long)b * C * 65536;
    for (int ic = 0; ic < C; ic++) {
        __syncthreads();
        const float* ip = inb + ((long)ic << 16);
        for (int idx = tid; idx < 324; idx += 128) {
            int r = idx / 18, c = idx - r * 18;
            int gh = h_base + r - 1, gw = w_base + c - 1;
            float v = 0.f;
            if ((unsigned)gh < 256u && (unsigned)gw < 256u) v = ip[(gh << 8) + gw];
            s_in[r][c] = v;
        }
        for (int idx = tid; idx < 144; idx += 128) {
            int oc = idx / 9, t = idx - oc * 9;
            float wv = w[((long)(oc_base + oc) * C + ic) * 9 + t];
            s_w2[oc][t] = make_float2(wv, wv);
        }
        __syncthreads();
        // e[r][i]: cols (w0+2i, w0+2i+1); o[r][0]=(w0+1,w0+2); o[r][1]=(w0+3,w0+4)
        float2 e[4][3], o[4][2];
#pragma unroll
        for (int r = 0; r < 4; r++) {
            e[r][0] = *(const float2*)&s_in[h0 + r][w0];
            e[r][1] = *(const float2*)&s_in[h0 + r][w0 + 2];
            e[r][2] = *(const float2*)&s_in[h0 + r][w0 + 4];
            o[r][0] = make_float2(e[r][0].y, e[r][1].x);
            o[r][1] = make_float2(e[r][1].y, e[r][2].x);
        }
#pragma unroll
        for (int j = 0; j < 4; j++) {
            int oc = ocq * 4 + j;
#pragma unroll
            for (int ky = 0; ky < 3; ky++) {
                float2 wv0 = s_w2[oc][ky * 3 + 0];
                float2 wv1 = s_w2[oc][ky * 3 + 1];
                float2 wv2 = s_w2[oc][ky * 3 + 2];
#pragma unroll
                for (int ih = 0; ih < 2; ih++) {
                    int r = ih + ky;
                    ffma2(acc[j][ih][0], e[r][0], wv0);
                    ffma2(acc[j][ih][1], e[r][1], wv0);
                    ffma2(acc[j][ih][0], o[r][0], wv1);
                    ffma2(acc[j][ih][1], o[r][1], wv1);
                    ffma2(acc[j][ih][0], e[r][1], wv2);
                    ffma2(acc[j][ih][1], e[r][2], wv2);
                }
            }
        }
    }
#pragma unroll
    for (int j = 0; j < 4; j++) {
        int oc = oc_base + ocq * 4 + j;
        float bv = bias[oc];
        float* op = out + (((long)b * C + oc) << 16);
#pragma unroll
        for (int ih = 0; ih < 2; ih++) {
            int gh = h_base + h0 + ih;
            int gw = w_base + w0;
            float4 v;
            v.x = fmaxf(acc[j][ih][0].x + bv, 0.f);
            v.y = fmaxf(acc[j][ih][0].y + bv, 0.f);
            v.z = fmaxf(acc[j][ih][1].x + bv, 0.f);
            v.w = fmaxf(acc[j][ih][1].y + bv, 0.f);
            *(float4*)&op[(gh << 8) + gw] = v;
        }
    }
}

// Final 1x1 conv: 16 -> 2 channels
__global__ void k_final(const float* __restrict__ x, const float* __restrict__ ow,
                        const float* __restrict__ ob, float* __restrict__ out) {
    int p = blockIdx.x * 256 + threadIdx.x;     // < B*65536
    int b = p >> 16;
    int pix = p & 65535;
    const float* xb = x + ((long)b << 20);      // b*16*65536
    float a0 = ob[0], a1 = ob[1];
#pragma unroll
    for (int i = 0; i < 16; i++) {
        float v = xb[(i << 16) + pix];
        a0 += v * ow[i];
        a1 += v * ow[16 + i];
    }
    out[(((long)b * 2) << 16) + pix] = a0;
    out[(((long)b * 2 + 1) << 16) + pix] = a1;
}

static void fno_stage(const float* x, const float* wr, const float* wi,
                      const float* bw, const float* bb, const float* skip,
                      float* out, int IC, int OC) {
    k_fwd_w<<<2 * IC * 32, 256>>>(x);
    k_fwd_h<<<IC, 256>>>();                       // 2*IC*4/8 = IC
    k_mix<<<2 * OC * 2, 256>>>(wr, wi, IC, OC);
    k_makeT<<<2 * OC * 4, 256>>>();
    dim3 g(512, (OC + 63) / 64, 2);
    k_fno_out<<<g, 128>>>(x, bw, bb, skip, out, IC, OC);
}

extern "C" void kernel_launch(void* const* d_in, const int* in_sizes, int n_in,
                              void* d_out, int out_size) {
    const float* x1 = (const float*)d_in[0];
    const float* x2 = (const float*)d_in[1];
    const float* x3 = (const float*)d_in[2];
    const float* x4 = (const float*)d_in[3];
    const float* x5 = (const float*)d_in[4];
    const float* f5_wr = (const float*)d_in[5];
    const float* f5_wi = (const float*)d_in[6];
    const float* f5_bw = (const float*)d_in[7];
    const float* f5_bb = (const float*)d_in[8];
    const float* f6_wr = (const float*)d_in[9];
    const float* f6_wi = (const float*)d_in[10];
    const float* f6_bw = (const float*)d_in[11];
    const float* f6_bb = (const float*)d_in[12];
    const float* f7_wr = (const float*)d_in[13];
    const float* f7_wi = (const float*)d_in[14];
    const float* f7_bw = (const float*)d_in[15];
    const float* f7_bb = (const float*)d_in[16];
    const float* f8_wr = (const float*)d_in[17];
    const float* f8_wi = (const float*)d_in[18];
    const float* f8_bw = (const float*)d_in[19];
    const float* f8_bb = (const float*)d_in[20];
    const float* c6_w = (const float*)d_in[21];
    const float* c6_b = (const float*)d_in[22];
    const float* c7_w = (const float*)d_in[23];
    const float* c7_b = (const float*)d_in[24];
    const float* c8_w = (const float*)d_in[25];
    const float* c8_b = (const float*)d_in[26];
    const float* c9_w = (const float*)d_in[27];
    const float* c9_b = (const float*)d_in[28];
    const float* ow = (const float*)d_in[29];
    const float* ob = (const float*)d_in[30];

    float *A = nullptr, *Bf = nullptr;
    cudaGetSymbolAddress((void**)&A, g_bufA);
    cudaGetSymbolAddress((void**)&Bf, g_bufB);

    k_tables<<<1, 256>>>();

    // x5u = fno(x5) + x4  -> A  (128 ch)
    fno_stage(x5, f5_wr, f5_wi, f5_bw, f5_bb, x4, A, 256, 128);

    // c6: 3 stages, 128 ch: A->B->A->B
    {
        int C = 128;
        dim3 g(16, 16, 2 * (C >> 4));
        float* cur = A; float* nxt = Bf;
        for (int i = 0; i < 3; i++) {
            k_conv3x3_relu<<<g, 128>>>(cur, c6_w + (long)i * C * C * 9, c6_b + i * C, nxt, C);
            float* t = cur; cur = nxt; nxt = t;
        }
    }
    // x6u = fno(Bf) + x3 -> A (64 ch)
    fno_stage(Bf, f6_wr, f6_wi, f6_bw, f6_bb, x3, A, 128, 64);

    // c7: 3 stages, 64 ch: A->B->A->B
    {
        int C = 64;
        dim3 g(16, 16, 2 * (C >> 4));
        float* cur = A; float* nxt = Bf;
        for (int i = 0; i < 3; i++) {
            k_conv3x3_relu<<<g, 128>>>(cur, c7_w + (long)i * C * C * 9, c7_b + i * C, nxt, C);
            float* t = cur; cur = nxt; nxt = t;
        }
    }
    // x7u = fno(Bf) + x2 -> A (32 ch)
    fno_stage(Bf, f7_wr, f7_wi, f7_bw, f7_bb, x2, A, 64, 32);

    // c8: 2 stages, 32 ch: A->B->A
    {
        int C = 32;
        dim3 g(16, 16, 2 * (C >> 4));
        float* cur = A; float* nxt = Bf;
        for (int i = 0; i < 2; i++) {
            k_conv3x3_relu<<<g, 128>>>(cur, c8_w + (long)i * C * C * 9, c8_b + i * C, nxt, C);
            float* t = cur; cur = nxt; nxt = t;
        }
    }
    // x8u = fno(A) + x1 -> B (16 ch)
    fno_stage(A, f8_wr, f8_wi, f8_bw, f8_bb, x1, Bf, 32, 16);

    // c9: 1 stage, 16 ch: B->A
    {
        int C = 16;
        dim3 g(16, 16, 2 * (C >> 4));
        k_conv3x3_relu<<<g, 128>>>(Bf, c9_w, c9_b, A, C);
    }
    // final 1x1: A -> d_out
    k_final<<<512, 256>>>(A, ow, ob, (float*)d_out);
}

// round 9
// speedup vs baseline: 1.1526x; 1.1526x over previous
#include <cuda_runtime.h>
#include <math.h>

// ---------------- device scratch (no dynamic allocation allowed) ----------------
__device__ __align__(16) float g_bufA[16777216];   // 2*128*256*256 floats = 64MB
__device__ __align__(16) float g_bufB[16777216];
__device__ __align__(16) float g_U[262144];        // Winograd weights: [ic][16][oc] up to 128x16x128
__device__ __align__(16) float2 g_P[524288];       // B*256*4*256
__device__ __align__(16) float2 g_xf[8192];        // B*256*16
__device__ __align__(16) float2 g_of[4096];        // B*128*16
__device__ __align__(16) float2 g_T[262144];       // B*128*256*4
__device__ float g_c256[256];
__device__ float g_s256[256];

__device__ __forceinline__ float wsum(float v) {
#pragma unroll
    for (int o = 16; o; o >>= 1) v += __shfl_xor_sync(0xffffffffu, v, o);
    return v;
}

// cos/sin(2*pi*t/256) tables built in double precision
__global__ void k_tables() {
    int t = threadIdx.x;
    double a = (double)t / 128.0;          // pi*t/128 = 2*pi*t/256
    g_c256[t] = (float)cospi(a);
    g_s256[t] = (float)sinpi(a);
}

// Stage 1: P[bi][l][h] = sum_w x[bi,h,w] * e^{-i 2pi l w/256}, l=0..3 (raw sums)
__global__ void k_fwd_w(const float* __restrict__ x) {
    __shared__ float cs[256], ss[256];
    int tid = threadIdx.x;
    cs[tid] = g_c256[tid];
    ss[tid] = g_s256[tid];
    __syncthreads();
    int warp = tid >> 5, lane = tid & 31;
    int row = blockIdx.x * 8 + warp;       // row < B*C*256 (grid exact)
    int bi = row >> 8;
    int h = row & 255;
    const float* xp = x + ((long)bi << 16) + (h << 8);
    float re0 = 0, re1 = 0, re2 = 0, re3 = 0, im1 = 0, im2 = 0, im3 = 0;
    for (int w = lane; w < 256; w += 32) {
        float v = xp[w];
        int m1 = w, m2 = (2 * w) & 255, m3 = (3 * w) & 255;
        re0 += v;
        re1 += v * cs[m1]; im1 -= v * ss[m1];
        re2 += v * cs[m2]; im2 -= v * ss[m2];
        re3 += v * cs[m3]; im3 -= v * ss[m3];
    }
    re0 = wsum(re0); re1 = wsum(re1); re2 = wsum(re2); re3 = wsum(re3);
    im1 = wsum(im1); im2 = wsum(im2); im3 = wsum(im3);
    if (lane == 0) {
        float2* Pp = g_P + ((long)bi << 10) + h;
        Pp[0]   = make_float2(re0, 0.f);
        Pp[256] = make_float2(re1, im1);
        Pp[512] = make_float2(re2, im2);
        Pp[768] = make_float2(re3, im3);
    }
}

// Stage 2: xf[bi][k][l] = sum_h P[bi][l][h] * e^{-i 2pi k h/256}, k=0..3
__global__ void k_fwd_h() {
    __shared__ float cs[256], ss[256];
    int tid = threadIdx.x;
    cs[tid] = g_c256[tid];
    ss[tid] = g_s256[tid];
    __syncthreads();
    int warp = tid >> 5, lane = tid & 31;
    int idx = blockIdx.x * 8 + warp;       // idx < B*C*4 (grid exact)
    int bi = idx >> 2;
    int l = idx & 3;
    const float2* Pp = g_P + ((long)bi << 10) + (l << 8);
    float xr0 = 0, xr1 = 0, xr2 = 0, xr3 = 0, xi0 = 0, xi1 = 0, xi2 = 0, xi3 = 0;
    for (int h = lane; h < 256; h += 32) {
        float2 p = Pp[h];
        int m1 = h, m2 = (2 * h) & 255, m3 = (3 * h) & 255;
        xr0 += p.x; xi0 += p.y;
        float c, s;
        c = cs[m1]; s = ss[m1]; xr1 += p.x * c + p.y * s; xi1 += p.y * c - p.x * s;
        c = cs[m2]; s = ss[m2]; xr2 += p.x * c + p.y * s; xi2 += p.y * c - p.x * s;
        c = cs[m3]; s = ss[m3]; xr3 += p.x * c + p.y * s; xi3 += p.y * c - p.x * s;
    }
    xr0 = wsum(xr0); xr1 = wsum(xr1); xr2 = wsum(xr2); xr3 = wsum(xr3);
    xi0 = wsum(xi0); xi1 = wsum(xi1); xi2 = wsum(xi2); xi3 = wsum(xi3);
    if (lane == 0) {
        float2* xfp = g_xf + ((long)bi << 4) + l;
        xfp[0]  = make_float2(xr0, xi0);
        xfp[4]  = make_float2(xr1, xi1);
        xfp[8]  = make_float2(xr2, xi2);
        xfp[12] = make_float2(xr3, xi3);
    }
}

// of[b][o][k][l] = sum_i xf[b][i][k][l] * (wr + i*wi)[i][o][k][l]
__global__ void k_mix(const float* __restrict__ wr, const float* __restrict__ wi,
                      int IC, int OC) {
    int tid = threadIdx.x;
    int warp = tid >> 5, lane = tid & 31;
    int idx = blockIdx.x * 8 + warp;       // idx < B*OC*16 (grid exact)
    int kl = idx & 15;
    int bo = idx >> 4;
    int b = bo / OC, o = bo - b * OC;
    float ar = 0, ai = 0;
    for (int i = lane; i < IC; i += 32) {
        float2 xv = g_xf[(((long)b * IC + i) << 4) + kl];
        long wb = ((long)i * OC + o) * 16 + kl;
        float wrv = wr[wb];
        float wiv = wi[wb];
        ar += xv.x * wrv - xv.y * wiv;
        ai += xv.x * wiv + xv.y * wrv;
    }
    ar = wsum(ar); ai = wsum(ai);
    if (lane == 0) g_of[idx] = make_float2(ar, ai);
}

// T[bo][h][l] = c_l/65536 * sum_k of[bo][k][l] * e^{+i 2pi k h/256}
__global__ void k_makeT() {
    int tid = blockIdx.x * 256 + threadIdx.x;   // < B*OC*1024 (grid exact)
    int l = tid & 3;
    int h = (tid >> 2) & 255;
    int bo = tid >> 10;
    float tr = 0, ti = 0;
#pragma unroll
    for (int k = 0; k < 4; k++) {
        float2 o = g_of[(bo << 4) + (k << 2) + l];
        int m = (k * h) & 255;
        float c = g_c256[m], s = g_s256[m];
        tr += o.x * c - o.y * s;
        ti += o.x * s + o.y * c;
    }
    float sc = (l == 0 ? 1.f : 2.f) * (1.f / 65536.f);
    g_T[tid] = make_float2(tr * sc, ti * sc);
}

// Fused: out = gelu( conv1x1(x,bw) + bb + synth(T) ) + skip
// GEMM tile 64oc x 128px, K-step 8, 8x8 register blocks, 128 threads.
__launch_bounds__(128, 4)
__global__ void k_fno_out(const float* __restrict__ x, const float* __restrict__ bw,
                          const float* __restrict__ bb, const float* __restrict__ skip,
                          float* __restrict__ out, int IC, int OC) {
    __shared__ __align__(16) float As[8][64];
    __shared__ __align__(16) float Xs[8][128];
    __shared__ float csS[256], ssS[256];
    int tid = threadIdx.x;
    csS[tid] = g_c256[tid]; csS[tid + 128] = g_c256[tid + 128];
    ssS[tid] = g_s256[tid]; ssS[tid + 128] = g_s256[tid + 128];
    int b = blockIdx.z;
    int oc_base = blockIdx.y * 64;
    int px_base = blockIdx.x * 128;
    const float* xb = x + (long)b * IC * 65536;
    int ocg = tid & 7, pxg = tid >> 3;
    int px0 = pxg * 8;
    float acc[8][8];
#pragma unroll
    for (int i = 0; i < 8; i++)
#pragma unroll
        for (int j = 0; j < 8; j++) acc[i][j] = 0.f;

    for (int k0 = 0; k0 < IC; k0 += 8) {
        __syncthreads();
#pragma unroll
        for (int t = tid; t < 512; t += 128) {
            int oc = t >> 3, kk = t & 7;
            int go = oc_base + oc;
            As[kk][oc] = (go < OC) ? bw[(long)go * IC + k0 + kk] : 0.f;
        }
#pragma unroll
        for (int t = tid; t < 1024; t += 128) {
            int kk = t >> 7, px = t & 127;
            Xs[kk][px] = xb[((long)(k0 + kk) << 16) + px_base + px];
        }
        __syncthreads();
#pragma unroll
        for (int kk = 0; kk < 8; kk++) {
            float4 a0 = *(const float4*)&As[kk][ocg * 8];
            float4 a1 = *(const float4*)&As[kk][ocg * 8 + 4];
            float4 v0 = *(const float4*)&Xs[kk][px0];
            float4 v1 = *(const float4*)&Xs[kk][px0 + 4];
            float av[8] = {a0.x, a0.y, a0.z, a0.w, a1.x, a1.y, a1.z, a1.w};
            float xv[8] = {v0.x, v0.y, v0.z, v0.w, v1.x, v1.y, v1.z, v1.w};
#pragma unroll
            for (int i = 0; i < 8; i++)
#pragma unroll
                for (int j = 0; j < 8; j++) acc[i][j] = fmaf(av[i], xv[j], acc[i][j]);
        }
    }
    // epilogue: synth + bias + exact gelu + skip
    int p00 = px_base + px0;
    int h = p00 >> 8;                       // 128-px tile never crosses a row
#pragma unroll
    for (int i = 0; i < 8; i++) {
        int oc = oc_base + ocg * 8 + i;
        if (oc >= OC) break;
        float bias = bb[oc];
        const float2* Tp = g_T + ((((long)b * OC + oc) << 8) + h) * 4;
        float4 t01 = *(const float4*)(Tp);      // T0.re, T0.im, T1.re, T1.im
        float4 t23 = *(const float4*)(Tp + 2);  // T2.re, T2.im, T3.re, T3.im
        long dstb = (((long)b * OC + oc) << 16);
#pragma unroll
        for (int j = 0; j < 8; j++) {
            int p = p00 + j;
            int w = p & 255;
            int m1 = w, m2 = (2 * w) & 255, m3 = (3 * w) & 255;
            float synth = t01.x;
            synth += t01.z * csS[m1] - t01.w * ssS[m1];
            synth += t23.x * csS[m2] - t23.y * ssS[m2];
            synth += t23.z * csS[m3] - t23.w * ssS[m3];
            float v = acc[i][j] + bias + synth;
            float g = 0.5f * v * (1.f + erff(v * 0.70710678118654752f));
            out[dstb + p] = g + skip[dstb + p];
        }
    }
}

// ---------------- Winograd F(2x2,3x3) path for big conv stages ----------------

// Weight transform: U[ic][xi][oc] = (G g G^T)[xi], g = w[oc][ic][3][3]
__global__ void k_wino_wt(const float* __restrict__ w, int C) {
    int idx = blockIdx.x * 256 + threadIdx.x;
    if (idx >= C * C) return;
    int oc = idx / C, ic = idx - oc * C;
    const float* g = w + (long)idx * 9;
    float r0[3] = {g[0], g[1], g[2]};
    float r1[3] = {g[3], g[4], g[5]};
    float r2[3] = {g[6], g[7], g[8]};
    float u[4][3];
#pragma unroll
    for (int j = 0; j < 3; j++) {
        u[0][j] = r0[j];
        u[1][j] = 0.5f * (r0[j] + r1[j] + r2[j]);
        u[2][j] = 0.5f * (r0[j] - r1[j] + r2[j]);
        u[3][j] = r2[j];
    }
#pragma unroll
    for (int i = 0; i < 4; i++) {
        float U0 = u[i][0];
        float U1 = 0.5f * (u[i][0] + u[i][1] + u[i][2]);
        float U2 = 0.5f * (u[i][0] - u[i][1] + u[i][2]);
        float U3 = u[i][2];
        long base = ((long)ic * 16 + i * 4) * C + oc;
        g_U[base]         = U0;
        g_U[base + C]     = U1;
        g_U[base + 2 * C] = U2;
        g_U[base + 3 * C] = U3;
    }
}

// Fused Winograd conv (+bias+ReLU). Block: 32 oc x 32 tiles (2 tile-rows x 16 tile-cols).
// 8 warps: warp w owns xi in {2w, 2w+1}; lane: ocg=lane>>2 (4 oc each), tg=lane&3 (8 tiles each).
__global__ __launch_bounds__(256, 2)
void k_wino(const float* __restrict__ in, const float* __restrict__ bias,
            float* __restrict__ out, int C) {
    __shared__ __align__(16) float sm[4096];
    float* sRaw = sm;          // [2][6][36]  (432)
    float* sV = sm + 448;      // [(ic*16+xi)*32 + tile]  (1024)
    float* sU = sm + 1472;     // [(ic*16+xi)*32 + oc]    (1024)

    int tid = threadIdx.x;
    int warp = tid >> 5, lane = tid & 31;
    int ocg = lane >> 2, tg = lane & 3;
    int nocb = C >> 5;
    int b = blockIdx.z / nocb;
    int ocb = blockIdx.z - b * nocb;
    int trb = blockIdx.y;                   // 0..63
    int tcb = blockIdx.x;                   // 0..7
    int row0 = (trb << 2) - 1;
    int col0 = (tcb << 5) - 1;
    const float* inb = in + (long)b * C * 65536;

    float acc[2][4][8];
#pragma unroll
    for (int a = 0; a < 2; a++)
#pragma unroll
        for (int o = 0; o < 4; o++)
#pragma unroll
            for (int t = 0; t < 8; t++) acc[a][o][t] = 0.f;

    // precompute phase-B job parameters
    int j_irow = tid & 3;
    int j_tile = (tid >> 2) & 31;
    int j_icl = tid >> 7;
    int j_trl = j_tile >> 4, j_tcl = j_tile & 15;
    int rA = (j_irow == 0) ? 0 : 1;
    int rB = (j_irow == 3) ? 3 : 2;
    float sA = (j_irow == 2) ? -1.f : 1.f;
    float sB = (j_irow == 1 || j_irow == 2) ? 1.f : -1.f;

    for (int icb = 0; icb < C; icb += 2) {
        __syncthreads();
        // stage raw input (2 ic x 6 x 34)
        for (int idx = tid; idx < 408; idx += 256) {
            int icl = idx / 204;
            int rem = idx - icl * 204;
            int rr = rem / 34;
            int cc = rem - rr * 34;
            int gh = row0 + rr, gw = col0 + cc;
            float v = 0.f;
            if ((unsigned)gh < 256u && (unsigned)gw < 256u)
                v = inb[(((long)(icb + icl)) << 16) + (gh << 8) + gw];
            sRaw[(icl * 6 + rr) * 36 + cc] = v;
        }
        // stage U (2 ic x 16 xi x 32 oc)
#pragma unroll
        for (int k = 0; k < 4; k++) {
            int idx = tid + (k << 8);
            int icl = idx >> 9;
            int rem = idx & 511;
            int xi = rem >> 5;
            int oc = rem & 31;
            sU[(icl * 16 + xi) * 32 + oc] =
                g_U[((long)(icb + icl) * 16 + xi) * C + (ocb << 5) + oc];
        }
        __syncthreads();
        // phase B: input transform, one (ic, tile, row) job per thread
        {
            const float* rb = &sRaw[(j_icl * 6 + (j_trl << 1)) * 36 + (j_tcl << 1)];
            float t0 = sA * rb[rA * 36 + 0] + sB * rb[rB * 36 + 0];
            float t1 = sA * rb[rA * 36 + 1] + sB * rb[rB * 36 + 1];
            float t2 = sA * rb[rA * 36 + 2] + sB * rb[rB * 36 + 2];
            float t3 = sA * rb[rA * 36 + 3] + sB * rb[rB * 36 + 3];
            float* vdst = &sV[(j_icl * 16 + (j_irow << 2)) * 32 + j_tile];
            vdst[0]  = t0 - t2;
            vdst[32] = t1 + t2;
            vdst[64] = t2 - t1;
            vdst[96] = t1 - t3;
        }
        __syncthreads();
        // phase C: GEMM micro-step
#pragma unroll
        for (int icl = 0; icl < 2; icl++)
#pragma unroll
            for (int xl = 0; xl < 2; xl++) {
                int xi = (warp << 1) + xl;
                const float* ub = &sU[(icl * 16 + xi) * 32 + (ocg << 2)];
                const float* vb = &sV[(icl * 16 + xi) * 32 + (tg << 3)];
                float4 Uf = *(const float4*)ub;
                float4 V0 = *(const float4*)vb;
                float4 V1 = *(const float4*)(vb + 4);
                float uv[4] = {Uf.x, Uf.y, Uf.z, Uf.w};
                float vv[8] = {V0.x, V0.y, V0.z, V0.w, V1.x, V1.y, V1.z, V1.w};
#pragma unroll
                for (int o = 0; o < 4; o++)
#pragma unroll
                    for (int t = 0; t < 8; t++)
                        acc[xl][o][t] = fmaf(uv[o], vv[t], acc[xl][o][t]);
            }
    }

    // epilogue: 4 rounds of 8 oc; reassemble M[16] via smem, output transform
    float* sM = sm;   // [xi*256 + ocl*32 + tile], 4096 floats
    for (int r = 0; r < 4; r++) {
        __syncthreads();
        if ((ocg >> 1) == r) {
#pragma unroll
            for (int xl = 0; xl < 2; xl++) {
                int xi = (warp << 1) + xl;
#pragma unroll
                for (int o = 0; o < 4; o++) {
                    int ocl = ((ocg & 1) << 2) + o;
                    float* dst = &sM[(xi << 8) + (ocl << 5) + (tg << 3)];
                    *(float4*)dst = make_float4(acc[xl][o][0], acc[xl][o][1],
                                                acc[xl][o][2], acc[xl][o][3]);
                    *(float4*)(dst + 4) = make_float4(acc[xl][o][4], acc[xl][o][5],
                                                      acc[xl][o][6], acc[xl][o][7]);
                }
            }
        }
        __syncthreads();
        {
            int oc8 = warp;
            int t = lane;
            int oc = (ocb << 5) + (r << 3) + oc8;
            float m[16];
#pragma unroll
            for (int xi = 0; xi < 16; xi++) m[xi] = sM[(xi << 8) + (oc8 << 5) + t];
            float z0[4], z1[4];
#pragma unroll
            for (int j = 0; j < 4; j++) {
                z0[j] = m[j] + m[4 + j] + m[8 + j];
                z1[j] = m[4 + j] - m[8 + j] - m[12 + j];
            }
            float bv = bias[oc];
            float y00 = fmaxf(z0[0] + z0[1] + z0[2] + bv, 0.f);
            float y01 = fmaxf(z0[1] - z0[2] - z0[3] + bv, 0.f);
            float y10 = fmaxf(z1[0] + z1[1] + z1[2] + bv, 0.f);
            float y11 = fmaxf(z1[1] - z1[2] - z1[3] + bv, 0.f);
            int trl = t >> 4, tcl = t & 15;
            int h = (trb << 2) + (trl << 1);
            int w = (tcb << 5) + (tcl << 1);
            float* op = out + (((long)b * C + oc) << 16) + (h << 8) + w;
            *(float2*)op = make_float2(y00, y01);
            *(float2*)(op + 256) = make_float2(y10, y11);
        }
    }
}

// Direct 3x3 SAME conv + bias + ReLU (for small C stages). 16oc x 16x16 tile.
__launch_bounds__(128)
__global__ void k_conv3x3_relu(const float* __restrict__ in, const float* __restrict__ w,
                               const float* __restrict__ bias, float* __restrict__ out,
                               int C) {
    __shared__ float s_in[18][19];
    __shared__ float s_w[16][10];
    int tid = threadIdx.x;
    int ocgc = C >> 4;
    int b = blockIdx.z / ocgc;
    int oc_base = (blockIdx.z - b * ocgc) << 4;
    int h_base = blockIdx.y << 4;
    int w_base = blockIdx.x << 4;
    int ocq = tid & 3;
    int pg = tid >> 2;
    int h0 = (pg >> 2) << 1;
    int w0 = (pg & 3) << 2;
    float acc[4][2][4];
#pragma unroll
    for (int j = 0; j < 4; j++)
#pragma unroll
        for (int ih = 0; ih < 2; ih++)
#pragma unroll
            for (int iw = 0; iw < 4; iw++) acc[j][ih][iw] = 0.f;
    const float* inb = in + (long)b * C * 65536;
    for (int ic = 0; ic < C; ic++) {
        __syncthreads();
        const float* ip = inb + ((long)ic << 16);
        for (int idx = tid; idx < 324; idx += 128) {
            int r = idx / 18, c = idx - r * 18;
            int gh = h_base + r - 1, gw = w_base + c - 1;
            float v = 0.f;
            if ((unsigned)gh < 256u && (unsigned)gw < 256u) v = ip[(gh << 8) + gw];
            s_in[r][c] = v;
        }
        for (int idx = tid; idx < 144; idx += 128) {
            int oc = idx / 9, t = idx - oc * 9;
            s_w[oc][t] = w[((long)(oc_base + oc) * C + ic) * 9 + t];
        }
        __syncthreads();
        float xr[4][6];
#pragma unroll
        for (int r = 0; r < 4; r++)
#pragma unroll
            for (int c = 0; c < 6; c++) xr[r][c] = s_in[h0 + r][w0 + c];
#pragma unroll
        for (int j = 0; j < 4; j++) {
            int oc = ocq * 4 + j;
#pragma unroll
            for (int ky = 0; ky < 3; ky++)
#pragma unroll
                for (int kx = 0; kx < 3; kx++) {
                    float wv = s_w[oc][ky * 3 + kx];
#pragma unroll
                    for (int ih = 0; ih < 2; ih++)
#pragma unroll
                        for (int iw = 0; iw < 4; iw++)
                            acc[j][ih][iw] = fmaf(wv, xr[ih + ky][iw + kx], acc[j][ih][iw]);
                }
        }
    }
#pragma unroll
    for (int j = 0; j < 4; j++) {
        int oc = oc_base + ocq * 4 + j;
        float bv = bias[oc];
        float* op = out + (((long)b * C + oc) << 16);
#pragma unroll
        for (int ih = 0; ih < 2; ih++) {
            int gh = h_base + h0 + ih;
#pragma unroll
            for (int iw = 0; iw < 4; iw++) {
                int gw = w_base + w0 + iw;
                float v = acc[j][ih][iw] + bv;
                op[(gh << 8) + gw] = fmaxf(v, 0.f);
            }
        }
    }
}

// Final 1x1 conv: 16 -> 2 channels
__global__ void k_final(const float* __restrict__ x, const float* __restrict__ ow,
                        const float* __restrict__ ob, float* __restrict__ out) {
    int p = blockIdx.x * 256 + threadIdx.x;     // < B*65536
    int b = p >> 16;
    int pix = p & 65535;
    const float* xb = x + ((long)b << 20);      // b*16*65536
    float a0 = ob[0], a1 = ob[1];
#pragma unroll
    for (int i = 0; i < 16; i++) {
        float v = xb[(i << 16) + pix];
        a0 += v * ow[i];
        a1 += v * ow[16 + i];
    }
    out[(((long)b * 2) << 16) + pix] = a0;
    out[(((long)b * 2 + 1) << 16) + pix] = a1;
}

static void fno_stage(const float* x, const float* wr, const float* wi,
                      const float* bw, const float* bb, const float* skip,
                      float* out, int IC, int OC) {
    k_fwd_w<<<2 * IC * 32, 256>>>(x);
    k_fwd_h<<<IC, 256>>>();                       // 2*IC*4/8 = IC
    k_mix<<<2 * OC * 2, 256>>>(wr, wi, IC, OC);
    k_makeT<<<2 * OC * 4, 256>>>();
    dim3 g(512, (OC + 63) / 64, 2);
    k_fno_out<<<g, 128>>>(x, bw, bb, skip, out, IC, OC);
}

static void wino_stage(const float* in, const float* w, const float* bias,
                       float* out, int C) {
    k_wino_wt<<<(C * C + 255) / 256, 256>>>(w, C);
    dim3 g(8, 64, 2 * (C >> 5));
    k_wino<<<g, 256>>>(in, bias, out, C);
}

extern "C" void kernel_launch(void* const* d_in, const int* in_sizes, int n_in,
                              void* d_out, int out_size) {
    const float* x1 = (const float*)d_in[0];
    const float* x2 = (const float*)d_in[1];
    const float* x3 = (const float*)d_in[2];
    const float* x4 = (const float*)d_in[3];
    const float* x5 = (const float*)d_in[4];
    const float* f5_wr = (const float*)d_in[5];
    const float* f5_wi = (const float*)d_in[6];
    const float* f5_bw = (const float*)d_in[7];
    const float* f5_bb = (const float*)d_in[8];
    const float* f6_wr = (const float*)d_in[9];
    const float* f6_wi = (const float*)d_in[10];
    const float* f6_bw = (const float*)d_in[11];
    const float* f6_bb = (const float*)d_in[12];
    const float* f7_wr = (const float*)d_in[13];
    const float* f7_wi = (const float*)d_in[14];
    const float* f7_bw = (const float*)d_in[15];
    const float* f7_bb = (const float*)d_in[16];
    const float* f8_wr = (const float*)d_in[17];
    const float* f8_wi = (const float*)d_in[18];
    const float* f8_bw = (const float*)d_in[19];
    const float* f8_bb = (const float*)d_in[20];
    const float* c6_w = (const float*)d_in[21];
    const float* c6_b = (const float*)d_in[22];
    const float* c7_w = (const float*)d_in[23];
    const float* c7_b = (const float*)d_in[24];
    const float* c8_w = (const float*)d_in[25];
    const float* c8_b = (const float*)d_in[26];
    const float* c9_w = (const float*)d_in[27];
    const float* c9_b = (const float*)d_in[28];
    const float* ow = (const float*)d_in[29];
    const float* ob = (const float*)d_in[30];

    float *A = nullptr, *Bf = nullptr;
    cudaGetSymbolAddress((void**)&A, g_bufA);
    cudaGetSymbolAddress((void**)&Bf, g_bufB);

    k_tables<<<1, 256>>>();

    // x5u = fno(x5) + x4  -> A  (128 ch)
    fno_stage(x5, f5_wr, f5_wi, f5_bw, f5_bb, x4, A, 256, 128);

    // c6: 3 Winograd stages, 128 ch: A->B->A->B
    {
        int C = 128;
        float* cur = A; float* nxt = Bf;
        for (int i = 0; i < 3; i++) {
            wino_stage(cur, c6_w + (long)i * C * C * 9, c6_b + i * C, nxt, C);
            float* t = cur; cur = nxt; nxt = t;
        }
    }
    // x6u = fno(Bf) + x3 -> A (64 ch)
    fno_stage(Bf, f6_wr, f6_wi, f6_bw, f6_bb, x3, A, 128, 64);

    // c7: 3 Winograd stages, 64 ch: A->B->A->B
    {
        int C = 64;
        float* cur = A; float* nxt = Bf;
        for (int i = 0; i < 3; i++) {
            wino_stage(cur, c7_w + (long)i * C * C * 9, c7_b + i * C, nxt, C);
            float* t = cur; cur = nxt; nxt = t;
        }
    }
    // x7u = fno(Bf) + x2 -> A (32 ch)
    fno_stage(Bf, f7_wr, f7_wi, f7_bw, f7_bb, x2, A, 64, 32);

    // c8: 2 direct stages, 32 ch: A->B->A
    {
        int C = 32;
        dim3 g(16, 16, 2 * (C >> 4));
        float* cur = A; float* nxt = Bf;
        for (int i = 0; i < 2; i++) {
            k_conv3x3_relu<<<g, 128>>>(cur, c8_w + (long)i * C * C * 9, c8_b + i * C, nxt, C);
            float* t = cur; cur = nxt; nxt = t;
        }
    }
    // x8u = fno(A) + x1 -> B (16 ch)
    fno_stage(A, f8_wr, f8_wi, f8_bw, f8_bb, x1, Bf, 32, 16);

    // c9: 1 direct stage, 16 ch: B->A
    {
        int C = 16;
        dim3 g(16, 16, 2 * (C >> 4));
        k_conv3x3_relu<<<g, 128>>>(Bf, c9_w, c9_b, A, C);
    }
    // final 1x1: A -> d_out
    k_final<<<512, 256>>>(A, ow, ob, (float*)d_out);
}